// round 4
// baseline (speedup 1.0000x reference)
#include <cuda_runtime.h>
#include <cuda_bf16.h>

// Problem constants (fixed shapes from reference)
constexpr int B = 256;
constexpr int P = 1024;
constexpr int G = 128;
constexpr float DIST_T2 = 500.0f * 500.0f;   // compare squared distance
constexpr float BBOX_THRESH = 0.1f;

constexpr int THREADS   = 128;
constexpr int CHUNK     = 128;                 // proposals per tile
constexpr int CHUNKS_PB = P / CHUNK;           // 8
constexpr int NTILES    = B * CHUNKS_PB;       // 2048
constexpr int NWORKERS  = 608;                 // ~4 CTAs/SM on 148-152 SMs

__device__ int g_tile_ctr;

__global__ void reset_ctr_kernel() { g_tile_ctr = 0; }

__global__ __launch_bounds__(THREADS) void proposal_kernel(
    const float* __restrict__ topk_index,    // [B,P,3]
    const float* __restrict__ topk_confs,    // [B,P]
    const float* __restrict__ bbox_preds,    // [B,P,2]
    const float* __restrict__ gt_3d,         // [B,G,3]
    const float* __restrict__ gt_bbox,       // [B,G,2]
    const int*   __restrict__ num_person,    // [B]
    float*       __restrict__ out)           // [B,P,7]
{
    __shared__ float4 sgt[G];                 // (gx,gy,gz,pad) -> LDS.128
    __shared__ float  sb0[G], sb1[G];
    __shared__ float  sout[CHUNK * 7];        // staged output tile (3584 B)
    __shared__ int    s_tile;

    const int tid = threadIdx.x;

    for (;;) {
        __syncthreads();   // protect sgt/sb/sout reuse from previous tile
        if (tid == 0) s_tile = atomicAdd(&g_tile_ctr, 1);
        __syncthreads();
        const int t = s_tile;
        if (t >= NTILES) break;

        const int b     = t >> 3;     // t / CHUNKS_PB
        const int chunk = t & 7;      // t % CHUNKS_PB

        // Stage this batch's GT data (128 threads <-> 128 slots).
        {
            const float* g3 = gt_3d + ((size_t)b * G + tid) * 3;
            sgt[tid] = make_float4(g3[0], g3[1], g3[2], 0.0f);
            const float* gb = gt_bbox + ((size_t)b * G + tid) * 2;
            sb0[tid] = gb[0];
            sb1[tid] = gb[1];
        }
        const int n = num_person[b];  // uniform per CTA -> zero divergence
        __syncthreads();

        const int    p  = chunk * CHUNK + tid;
        const size_t bp = (size_t)b * P + p;

        const float x = topk_index[bp * 3 + 0];
        const float y = topk_index[bp * 3 + 1];
        const float z = topk_index[bp * 3 + 2];

        // Argmin over valid GT slots; strict < keeps first-index tie-break
        // (JAX argmin). d2 compare is exact vs sqrt-compare (monotone).
        float best = 3.402823466e38f;
        int   bg   = 0;
        #pragma unroll 4
        for (int g = 0; g < n; ++g) {
            const float4 gt = sgt[g];
            const float dx = x - gt.x;
            const float dy = y - gt.y;
            const float dz = z - gt.z;
            const float d2 = fmaf(dx, dx, fmaf(dy, dy, dz * dz));
            if (d2 < best) { best = d2; bg = g; }
        }

        const float p2g = (best > DIST_T2) ? -1.0f : (float)bg;

        const float mb0 = sb0[bg];
        const float mb1 = sb1[bg];
        const float q0  = bbox_preds[bp * 2 + 0];
        const float q1  = bbox_preds[bp * 2 + 1];

        const bool cond = (p2g >= 0.0f) &&
                          ((q0 < mb0 - BBOX_THRESH) || (q1 < mb1 - BBOX_THRESH));

        // Stage the 7 outputs in shared (stride 7 -> bank-conflict-free STS),
        // then copy the contiguous 3584B tile to GMEM as float4 (coalesced).
        float* so = sout + tid * 7;
        so[0] = x;
        so[1] = y;
        so[2] = z;
        so[3] = p2g;
        so[4] = topk_confs[bp];
        so[5] = cond ? mb0 : q0;
        so[6] = cond ? mb1 : q1;
        __syncthreads();

        const size_t tile_base = ((size_t)b * P + (size_t)chunk * CHUNK) * 7;
        float4*       dst = reinterpret_cast<float4*>(out + tile_base);
        const float4* src = reinterpret_cast<const float4*>(sout);
        #pragma unroll
        for (int i = 0; i < (CHUNK * 7) / 4 / THREADS + 1; ++i) {
            const int idx = tid + i * THREADS;
            if (idx < (CHUNK * 7) / 4) dst[idx] = src[idx];
        }
    }
}

extern "C" void kernel_launch(void* const* d_in, const int* in_sizes, int n_in,
                              void* d_out, int out_size) {
    const float* topk_index  = (const float*)d_in[0];  // [B,P,3]
    const float* topk_confs  = (const float*)d_in[1];  // [B,P]
    const float* bbox_preds  = (const float*)d_in[2];  // [B,P,2]
    const float* gt_3d       = (const float*)d_in[3];  // [B,G,3]
    const float* gt_bbox     = (const float*)d_in[4];  // [B,G,2]
    const int*   num_person  = (const int*)  d_in[5];  // [B]
    float*       out         = (float*)d_out;          // [B,P,7]

    reset_ctr_kernel<<<1, 1>>>();
    proposal_kernel<<<NWORKERS, THREADS>>>(topk_index, topk_confs, bbox_preds,
                                           gt_3d, gt_bbox, num_person, out);
}

// round 5
// speedup vs baseline: 1.0625x; 1.0625x over previous
#include <cuda_runtime.h>
#include <cuda_bf16.h>

// Problem constants (fixed shapes from reference)
constexpr int B = 256;
constexpr int P = 1024;
constexpr int G = 128;
constexpr float DIST_T2 = 500.0f * 500.0f;   // compare squared distance
constexpr float BBOX_THRESH = 0.1f;
constexpr float SENTINEL = 1.0e15f;          // padded GT slot -> d2 ~ 3e30, never wins

constexpr int THREADS = 256;
constexpr int PROPS_PER_CTA = THREADS;       // 1 proposal / thread

__global__ __launch_bounds__(THREADS) void proposal_kernel(
    const float* __restrict__ topk_index,    // [B,P,3]
    const float* __restrict__ topk_confs,    // [B,P]
    const float* __restrict__ bbox_preds,    // [B,P,2]
    const float* __restrict__ gt_3d,         // [B,G,3]
    const float* __restrict__ gt_bbox,       // [B,G,2]
    const int*   __restrict__ num_person,    // [B]
    float*       __restrict__ out)           // [B,P,7]
{
    __shared__ float4 sgt[G];                 // (gx,gy,gz,pad): one LDS.128/iter
    __shared__ float  sb0[G], sb1[G];
    __shared__ float  sout[THREADS * 7];      // staged output tile (7168 B)

    const int b   = blockIdx.y;
    const int tid = threadIdx.x;
    const int n   = num_person[b];            // broadcast LDG

    // Stage GT; pad slots g >= n with a far sentinel so a uniform
    // compile-time 128-iteration loop is exact: real slots (g < n, n >= 1)
    // come first, so sentinels can never win the strict-< argmin.
    if (tid < G) {
        float4 v = make_float4(SENTINEL, SENTINEL, SENTINEL, 0.0f);
        if (tid < n) {
            const float* g3 = gt_3d + ((size_t)b * G + tid) * 3;
            v = make_float4(g3[0], g3[1], g3[2], 0.0f);
        }
        sgt[tid] = v;
        const float* gb = gt_bbox + ((size_t)b * G + tid) * 2;
        sb0[tid] = gb[0];
        sb1[tid] = gb[1];
    }
    __syncthreads();

    const int    p  = blockIdx.x * PROPS_PER_CTA + tid;
    const size_t bp = (size_t)b * P + p;

    const float x = topk_index[bp * 3 + 0];
    const float y = topk_index[bp * 3 + 1];
    const float z = topk_index[bp * 3 + 2];

    // Exact argmin, strict < -> first-index tie-break (matches JAX argmin).
    // d2-vs-d2 and d2-vs-500^2 compares are exact equivalents of the
    // reference's sqrt compares (sqrt is monotone).
    float best = 3.402823466e38f;
    int   bg   = 0;
    #pragma unroll
    for (int g = 0; g < G; ++g) {
        const float4 gt = sgt[g];
        const float dx = x - gt.x;
        const float dy = y - gt.y;
        const float dz = z - gt.z;
        const float d2 = fmaf(dx, dx, fmaf(dy, dy, dz * dz));
        if (d2 < best) { best = d2; bg = g; }
    }

    const float p2g = (best > DIST_T2) ? -1.0f : (float)bg;

    const float mb0 = sb0[bg];
    const float mb1 = sb1[bg];
    const float q0  = bbox_preds[bp * 2 + 0];
    const float q1  = bbox_preds[bp * 2 + 1];

    const bool cond = (p2g >= 0.0f) &&
                      ((q0 < mb0 - BBOX_THRESH) || (q1 < mb1 - BBOX_THRESH));

    // Stage the 7 outputs in shared (stride 7 is coprime with 32 banks ->
    // conflict-free STS), then copy the contiguous 7168B tile as float4.
    float* so = sout + tid * 7;
    so[0] = x;
    so[1] = y;
    so[2] = z;
    so[3] = p2g;
    so[4] = topk_confs[bp];
    so[5] = cond ? mb0 : q0;
    so[6] = cond ? mb1 : q1;
    __syncthreads();

    const size_t tile_base = ((size_t)b * P + (size_t)blockIdx.x * PROPS_PER_CTA) * 7;
    float4*       dst = reinterpret_cast<float4*>(out + tile_base);
    const float4* src = reinterpret_cast<const float4*>(sout);
    constexpr int NVEC = THREADS * 7 / 4;     // 448
    #pragma unroll
    for (int i = 0; i < 2; ++i) {
        const int idx = tid + i * THREADS;
        if (idx < NVEC) dst[idx] = src[idx];
    }
}

extern "C" void kernel_launch(void* const* d_in, const int* in_sizes, int n_in,
                              void* d_out, int out_size) {
    const float* topk_index  = (const float*)d_in[0];  // [B,P,3]
    const float* topk_confs  = (const float*)d_in[1];  // [B,P]
    const float* bbox_preds  = (const float*)d_in[2];  // [B,P,2]
    const float* gt_3d       = (const float*)d_in[3];  // [B,G,3]
    const float* gt_bbox     = (const float*)d_in[4];  // [B,G,2]
    const int*   num_person  = (const int*)  d_in[5];  // [B]
    float*       out         = (float*)d_out;          // [B,P,7]

    dim3 grid(P / PROPS_PER_CTA, B);
    proposal_kernel<<<grid, THREADS>>>(topk_index, topk_confs, bbox_preds,
                                       gt_3d, gt_bbox, num_person, out);
}

// round 6
// speedup vs baseline: 1.3750x; 1.2941x over previous
#include <cuda_runtime.h>
#include <cuda_bf16.h>
#include <cstdint>

// Problem constants (fixed shapes from reference)
constexpr int B = 256;
constexpr int P = 1024;
constexpr int G = 128;
constexpr float DIST_T2 = 500.0f * 500.0f;   // compare squared distance
constexpr float BBOX_THRESH = 0.1f;

constexpr int THREADS = 128;
constexpr int IPROP   = 2;                     // proposals per thread (f32x2 lanes)
constexpr int PROPS_PER_CTA = THREADS * IPROP; // 256

// ---- packed f32x2 helpers (sm_103a; .rn packed ops == 2x scalar rn ops) ----
__device__ __forceinline__ uint64_t pack2(float lo, float hi) {
    uint64_t r;
    asm("mov.b64 %0, {%1, %2};" : "=l"(r) : "f"(lo), "f"(hi));
    return r;
}
__device__ __forceinline__ void unpack2(uint64_t v, float& lo, float& hi) {
    asm("mov.b64 {%0, %1}, %2;" : "=f"(lo), "=f"(hi) : "l"(v));
}
__device__ __forceinline__ uint64_t add2(uint64_t a, uint64_t b) {
    uint64_t r;
    asm("add.rn.f32x2 %0, %1, %2;" : "=l"(r) : "l"(a), "l"(b));
    return r;
}
__device__ __forceinline__ uint64_t mul2(uint64_t a, uint64_t b) {
    uint64_t r;
    asm("mul.rn.f32x2 %0, %1, %2;" : "=l"(r) : "l"(a), "l"(b));
    return r;
}
__device__ __forceinline__ uint64_t fma2(uint64_t a, uint64_t b, uint64_t c) {
    uint64_t r;
    asm("fma.rn.f32x2 %0, %1, %2, %3;" : "=l"(r) : "l"(a), "l"(b), "l"(c));
    return r;
}

__global__ __launch_bounds__(THREADS) void proposal_kernel(
    const float* __restrict__ topk_index,    // [B,P,3]
    const float* __restrict__ topk_confs,    // [B,P]
    const float* __restrict__ bbox_preds,    // [B,P,2]
    const float* __restrict__ gt_3d,         // [B,G,3]
    const float* __restrict__ gt_bbox,       // [B,G,2]
    const int*   __restrict__ num_person,    // [B]
    float*       __restrict__ out)           // [B,P,7]
{
    // GT staged pre-negated & lane-duplicated for packed adds:
    //   sxy[g] = (-gx,-gx,-gy,-gy)   (one LDS.128)
    //   szz[g] = (-gz,-gz)           (one LDS.64)
    __shared__ float4 sxy[G];
    __shared__ float2 szz[G];
    __shared__ float  sb0[G], sb1[G];
    __shared__ float  sout[PROPS_PER_CTA * 7];   // staged output (7168 B)

    const int b   = blockIdx.y;
    const int tid = threadIdx.x;
    const int n   = num_person[b];               // uniform per CTA

    {
        const float* g3 = gt_3d + ((size_t)b * G + tid) * 3;
        const float ngx = -g3[0], ngy = -g3[1], ngz = -g3[2];
        sxy[tid] = make_float4(ngx, ngx, ngy, ngy);
        szz[tid] = make_float2(ngz, ngz);
        const float* gb = gt_bbox + ((size_t)b * G + tid) * 2;
        sb0[tid] = gb[0];
        sb1[tid] = gb[1];
    }
    __syncthreads();

    // Two proposals per thread: p0 = base+tid, p1 = base+tid+128 (coalesced)
    const int    pbase = blockIdx.x * PROPS_PER_CTA + tid;
    const size_t bp0   = (size_t)b * P + pbase;
    const size_t bp1   = bp0 + THREADS;

    const float x0 = topk_index[bp0 * 3 + 0];
    const float y0 = topk_index[bp0 * 3 + 1];
    const float z0 = topk_index[bp0 * 3 + 2];
    const float x1 = topk_index[bp1 * 3 + 0];
    const float y1 = topk_index[bp1 * 3 + 1];
    const float z1 = topk_index[bp1 * 3 + 2];

    // Hoist the per-proposal gmem loads to overlap their latency with the loop.
    const float q00 = bbox_preds[bp0 * 2 + 0];
    const float q01 = bbox_preds[bp0 * 2 + 1];
    const float q10 = bbox_preds[bp1 * 2 + 0];
    const float q11 = bbox_preds[bp1 * 2 + 1];
    const float c0  = topk_confs[bp0];
    const float c1  = topk_confs[bp1];

    const uint64_t X2 = pack2(x0, x1);
    const uint64_t Y2 = pack2(y0, y1);
    const uint64_t Z2 = pack2(z0, z1);

    // Exact argmin, strict < -> first-index tie-break (JAX argmin).
    // Packed .rn f32x2 math is bit-identical to the scalar rn sequence.
    float besta = 3.402823466e38f, bestb = 3.402823466e38f;
    int   bga = 0, bgb = 0;
    #pragma unroll 4
    for (int g = 0; g < n; ++g) {
        const uint64_t* pxy = reinterpret_cast<const uint64_t*>(&sxy[g]);
        const uint64_t  gnx = pxy[0];                                  // (-gx,-gx)
        const uint64_t  gny = pxy[1];                                  // (-gy,-gy)
        const uint64_t  gnz = *reinterpret_cast<const uint64_t*>(&szz[g]);

        const uint64_t dx = add2(X2, gnx);
        const uint64_t dy = add2(Y2, gny);
        const uint64_t dz = add2(Z2, gnz);
        const uint64_t d2 = fma2(dx, dx, fma2(dy, dy, mul2(dz, dz)));

        float d2a, d2b;
        unpack2(d2, d2a, d2b);          // free: reads the register pair
        if (d2a < besta) { besta = d2a; bga = g; }
        if (d2b < bestb) { bestb = d2b; bgb = g; }
    }

    const float p2ga = (besta > DIST_T2) ? -1.0f : (float)bga;
    const float p2gb = (bestb > DIST_T2) ? -1.0f : (float)bgb;

    const float mb00 = sb0[bga], mb01 = sb1[bga];
    const float mb10 = sb0[bgb], mb11 = sb1[bgb];

    const bool conda = (p2ga >= 0.0f) &&
                       ((q00 < mb00 - BBOX_THRESH) || (q01 < mb01 - BBOX_THRESH));
    const bool condb = (p2gb >= 0.0f) &&
                       ((q10 < mb10 - BBOX_THRESH) || (q11 < mb11 - BBOX_THRESH));

    // Stage outputs in shared (stride 7 coprime 32 -> conflict-free STS),
    // then copy the contiguous tile to GMEM as float4 (coalesced STG.128).
    {
        float* so = sout + tid * 7;
        so[0] = x0; so[1] = y0; so[2] = z0;
        so[3] = p2ga; so[4] = c0;
        so[5] = conda ? mb00 : q00;
        so[6] = conda ? mb01 : q01;
    }
    {
        float* so = sout + (tid + THREADS) * 7;
        so[0] = x1; so[1] = y1; so[2] = z1;
        so[3] = p2gb; so[4] = c1;
        so[5] = condb ? mb10 : q10;
        so[6] = condb ? mb11 : q11;
    }
    __syncthreads();

    const size_t tile_base = ((size_t)b * P + (size_t)blockIdx.x * PROPS_PER_CTA) * 7;
    float4*       dst = reinterpret_cast<float4*>(out + tile_base);
    const float4* src = reinterpret_cast<const float4*>(sout);
    constexpr int NVEC = PROPS_PER_CTA * 7 / 4;   // 448
    #pragma unroll
    for (int i = 0; i < 4; ++i) {
        const int idx = tid + i * THREADS;
        if (idx < NVEC) dst[idx] = src[idx];
    }
}

extern "C" void kernel_launch(void* const* d_in, const int* in_sizes, int n_in,
                              void* d_out, int out_size) {
    const float* topk_index  = (const float*)d_in[0];  // [B,P,3]
    const float* topk_confs  = (const float*)d_in[1];  // [B,P]
    const float* bbox_preds  = (const float*)d_in[2];  // [B,P,2]
    const float* gt_3d       = (const float*)d_in[3];  // [B,G,3]
    const float* gt_bbox     = (const float*)d_in[4];  // [B,G,2]
    const int*   num_person  = (const int*)  d_in[5];  // [B]
    float*       out         = (float*)d_out;          // [B,P,7]

    dim3 grid(P / PROPS_PER_CTA, B);
    proposal_kernel<<<grid, THREADS>>>(topk_index, topk_confs, bbox_preds,
                                       gt_3d, gt_bbox, num_person, out);
}

// round 7
// speedup vs baseline: 1.4025x; 1.0200x over previous
#include <cuda_runtime.h>
#include <cuda_bf16.h>
#include <cstdint>

// Problem constants (fixed shapes from reference)
constexpr int B = 256;
constexpr int P = 1024;
constexpr int G = 128;
constexpr float DIST_T2 = 500.0f * 500.0f;   // compare squared distance
constexpr float BBOX_THRESH = 0.1f;

constexpr int THREADS = 64;                    // small CTAs -> fine-grain balance
constexpr int IPROP   = 2;                     // proposals per thread (f32x2 lanes)
constexpr int PROPS_PER_CTA = THREADS * IPROP; // 128
constexpr int CHUNKS_PB = P / PROPS_PER_CTA;   // 8

// ---- packed f32x2 helpers (sm_103a; .rn packed ops == 2x scalar rn ops) ----
__device__ __forceinline__ uint64_t pack2(float lo, float hi) {
    uint64_t r;
    asm("mov.b64 %0, {%1, %2};" : "=l"(r) : "f"(lo), "f"(hi));
    return r;
}
__device__ __forceinline__ void unpack2(uint64_t v, float& lo, float& hi) {
    asm("mov.b64 {%0, %1}, %2;" : "=f"(lo), "=f"(hi) : "l"(v));
}
__device__ __forceinline__ uint64_t add2(uint64_t a, uint64_t b) {
    uint64_t r;
    asm("add.rn.f32x2 %0, %1, %2;" : "=l"(r) : "l"(a), "l"(b));
    return r;
}
__device__ __forceinline__ uint64_t mul2(uint64_t a, uint64_t b) {
    uint64_t r;
    asm("mul.rn.f32x2 %0, %1, %2;" : "=l"(r) : "l"(a), "l"(b));
    return r;
}
__device__ __forceinline__ uint64_t fma2(uint64_t a, uint64_t b, uint64_t c) {
    uint64_t r;
    asm("fma.rn.f32x2 %0, %1, %2, %3;" : "=l"(r) : "l"(a), "l"(b), "l"(c));
    return r;
}

__global__ __launch_bounds__(THREADS) void proposal_kernel(
    const float* __restrict__ topk_index,    // [B,P,3]
    const float* __restrict__ topk_confs,    // [B,P]
    const float* __restrict__ bbox_preds,    // [B,P,2]
    const float* __restrict__ gt_3d,         // [B,G,3]
    const float* __restrict__ gt_bbox,       // [B,G,2]
    const int*   __restrict__ num_person,    // [B]
    float*       __restrict__ out)           // [B,P,7]
{
    // GT staged pre-negated & lane-duplicated, 32B per slot so the f32x2
    // operands come straight out of aligned register pairs:
    //   sgt[g] = { (-gx,-gx), (-gy,-gy), (-gz,-gz), pad }
    __shared__ ulonglong2 sgt[G][2];
    __shared__ float      sb0[G], sb1[G];
    __shared__ float      sout[PROPS_PER_CTA * 7];   // staged output (3584 B)

    const int tid = threadIdx.x;
    const int b     = blockIdx.x >> 3;       // 8 chunks per batch
    const int chunk = blockIdx.x & 7;
    const int n     = num_person[b];          // uniform per CTA

    #pragma unroll
    for (int g0 = tid; g0 < G; g0 += THREADS) {
        const float* g3 = gt_3d + ((size_t)b * G + g0) * 3;
        const float ngx = -g3[0], ngy = -g3[1], ngz = -g3[2];
        sgt[g0][0] = make_ulonglong2(pack2(ngx, ngx), pack2(ngy, ngy));
        sgt[g0][1] = make_ulonglong2(pack2(ngz, ngz), 0ull);
        const float* gb = gt_bbox + ((size_t)b * G + g0) * 2;
        sb0[g0] = gb[0];
        sb1[g0] = gb[1];
    }
    __syncthreads();

    // Two proposals per thread: p0 = base+tid, p1 = base+tid+64 (coalesced)
    const int    pbase = chunk * PROPS_PER_CTA + tid;
    const size_t bp0   = (size_t)b * P + pbase;
    const size_t bp1   = bp0 + THREADS;

    const float x0 = topk_index[bp0 * 3 + 0];
    const float y0 = topk_index[bp0 * 3 + 1];
    const float z0 = topk_index[bp0 * 3 + 2];
    const float x1 = topk_index[bp1 * 3 + 0];
    const float y1 = topk_index[bp1 * 3 + 1];
    const float z1 = topk_index[bp1 * 3 + 2];

    // Hoist per-proposal gmem loads so their latency overlaps the loop.
    const float q00 = bbox_preds[bp0 * 2 + 0];
    const float q01 = bbox_preds[bp0 * 2 + 1];
    const float q10 = bbox_preds[bp1 * 2 + 0];
    const float q11 = bbox_preds[bp1 * 2 + 1];
    const float c0  = topk_confs[bp0];
    const float c1  = topk_confs[bp1];

    const uint64_t X2 = pack2(x0, x1);
    const uint64_t Y2 = pack2(y0, y1);
    const uint64_t Z2 = pack2(z0, z1);

    // Exact argmin, strict < -> first-index tie-break (JAX argmin).
    // Packed .rn f32x2 math is bit-identical to the scalar rn sequence.
    float besta = 3.402823466e38f, bestb = 3.402823466e38f;
    int   bga = 0, bgb = 0;
    #pragma unroll 4
    for (int g = 0; g < n; ++g) {
        const ulonglong2 v0 = sgt[g][0];     // one LDS.128: (-gx dup, -gy dup)
        const uint64_t   gnz = sgt[g][1].x;  // one LDS.64:  (-gz dup)

        const uint64_t dx = add2(X2, v0.x);
        const uint64_t dy = add2(Y2, v0.y);
        const uint64_t dz = add2(Z2, gnz);
        const uint64_t d2 = fma2(dx, dx, fma2(dy, dy, mul2(dz, dz)));

        float d2a, d2b;
        unpack2(d2, d2a, d2b);
        if (d2a < besta) { besta = d2a; bga = g; }
        if (d2b < bestb) { bestb = d2b; bgb = g; }
    }

    const float p2ga = (besta > DIST_T2) ? -1.0f : (float)bga;
    const float p2gb = (bestb > DIST_T2) ? -1.0f : (float)bgb;

    const float mb00 = sb0[bga], mb01 = sb1[bga];
    const float mb10 = sb0[bgb], mb11 = sb1[bgb];

    const bool conda = (p2ga >= 0.0f) &&
                       ((q00 < mb00 - BBOX_THRESH) || (q01 < mb01 - BBOX_THRESH));
    const bool condb = (p2gb >= 0.0f) &&
                       ((q10 < mb10 - BBOX_THRESH) || (q11 < mb11 - BBOX_THRESH));

    // Stage outputs in shared (stride 7 coprime 32 -> conflict-free STS),
    // then copy the contiguous tile to GMEM as float4 (coalesced STG.128).
    {
        float* so = sout + tid * 7;
        so[0] = x0; so[1] = y0; so[2] = z0;
        so[3] = p2ga; so[4] = c0;
        so[5] = conda ? mb00 : q00;
        so[6] = conda ? mb01 : q01;
    }
    {
        float* so = sout + (tid + THREADS) * 7;
        so[0] = x1; so[1] = y1; so[2] = z1;
        so[3] = p2gb; so[4] = c1;
        so[5] = condb ? mb10 : q10;
        so[6] = condb ? mb11 : q11;
    }
    __syncthreads();

    const size_t tile_base = ((size_t)b * P + (size_t)chunk * PROPS_PER_CTA) * 7;
    float4*       dst = reinterpret_cast<float4*>(out + tile_base);
    const float4* src = reinterpret_cast<const float4*>(sout);
    constexpr int NVEC = PROPS_PER_CTA * 7 / 4;   // 224
    #pragma unroll
    for (int i = 0; i < NVEC / THREADS + 1; ++i) {
        const int idx = tid + i * THREADS;
        if (idx < NVEC) dst[idx] = src[idx];
    }
}

extern "C" void kernel_launch(void* const* d_in, const int* in_sizes, int n_in,
                              void* d_out, int out_size) {
    const float* topk_index  = (const float*)d_in[0];  // [B,P,3]
    const float* topk_confs  = (const float*)d_in[1];  // [B,P]
    const float* bbox_preds  = (const float*)d_in[2];  // [B,P,2]
    const float* gt_3d       = (const float*)d_in[3];  // [B,G,3]
    const float* gt_bbox     = (const float*)d_in[4];  // [B,G,2]
    const int*   num_person  = (const int*)  d_in[5];  // [B]
    float*       out         = (float*)d_out;          // [B,P,7]

    proposal_kernel<<<B * CHUNKS_PB, THREADS>>>(topk_index, topk_confs, bbox_preds,
                                                gt_3d, gt_bbox, num_person, out);
}

// round 8
// speedup vs baseline: 1.4060x; 1.0025x over previous
#include <cuda_runtime.h>
#include <cuda_bf16.h>
#include <cstdint>

// Problem constants (fixed shapes from reference)
constexpr int B = 256;
constexpr int P = 1024;
constexpr int G = 128;
constexpr float DIST_T2 = 500.0f * 500.0f;   // compare squared distance
constexpr float BBOX_THRESH = 0.1f;
constexpr float SENTINEL = 1.0e15f;          // d2 ~ 3e30: finite, never beats a real slot

constexpr int THREADS = 128;                  // 1 proposal/thread -> max TLP
constexpr int PROPS_PER_CTA = THREADS;        // 128
constexpr int CHUNKS_PB = P / PROPS_PER_CTA;  // 8

// ---- packed f32x2 helpers (sm_103a; .rn packed ops == 2x scalar rn ops) ----
__device__ __forceinline__ uint64_t pack2(float lo, float hi) {
    uint64_t r;
    asm("mov.b64 %0, {%1, %2};" : "=l"(r) : "f"(lo), "f"(hi));
    return r;
}
__device__ __forceinline__ void unpack2(uint64_t v, float& lo, float& hi) {
    asm("mov.b64 {%0, %1}, %2;" : "=f"(lo), "=f"(hi) : "l"(v));
}
__device__ __forceinline__ uint64_t add2(uint64_t a, uint64_t b) {
    uint64_t r;
    asm("add.rn.f32x2 %0, %1, %2;" : "=l"(r) : "l"(a), "l"(b));
    return r;
}
__device__ __forceinline__ uint64_t mul2(uint64_t a, uint64_t b) {
    uint64_t r;
    asm("mul.rn.f32x2 %0, %1, %2;" : "=l"(r) : "l"(a), "l"(b));
    return r;
}
__device__ __forceinline__ uint64_t fma2(uint64_t a, uint64_t b, uint64_t c) {
    uint64_t r;
    asm("fma.rn.f32x2 %0, %1, %2, %3;" : "=l"(r) : "l"(a), "l"(b), "l"(c));
    return r;
}

__global__ __launch_bounds__(THREADS) void proposal_kernel(
    const float* __restrict__ topk_index,    // [B,P,3]
    const float* __restrict__ topk_confs,    // [B,P]
    const float* __restrict__ bbox_preds,    // [B,P,2]
    const float* __restrict__ gt_3d,         // [B,G,3]
    const float* __restrict__ gt_bbox,       // [B,G,2]
    const int*   __restrict__ num_person,    // [B]
    float*       __restrict__ out)           // [B,P,7]
{
    // GT staged as PAIRS, negated, so one f32x2 op handles 2 GT points:
    //   spair[i] = { (-gx_{2i},-gx_{2i+1}), (-gy pair), (-gz pair), pad }
    __shared__ ulonglong2 spair[G / 2][2];     // 32B/record: LDS.128 + LDS.64
    __shared__ float      sb0[G], sb1[G];
    __shared__ float      sout[PROPS_PER_CTA * 7];

    const int tid   = threadIdx.x;
    const int b     = blockIdx.x >> 3;         // 8 chunks per batch
    const int chunk = blockIdx.x & 7;
    const int n     = num_person[b];           // uniform per CTA

    // Stage GT (tid == g, THREADS == G). Slots g >= n get the sentinel so a
    // remainder-free unroll-4 pair loop is exact: real slots (g < n, n >= 1)
    // come first, and max real d2 ~ 1.9e8 << sentinel d2 ~ 3e30.
    {
        float ngx = -SENTINEL, ngy = -SENTINEL, ngz = -SENTINEL;
        if (tid < n) {
            const float* g3 = gt_3d + ((size_t)b * G + tid) * 3;
            ngx = -g3[0]; ngy = -g3[1]; ngz = -g3[2];
        }
        float* sp = reinterpret_cast<float*>(spair) + (tid >> 1) * 8 + (tid & 1);
        sp[0] = ngx;   // x lane
        sp[2] = ngy;   // y lane
        sp[4] = ngz;   // z lane
        const float* gb = gt_bbox + ((size_t)b * G + tid) * 2;
        sb0[tid] = gb[0];
        sb1[tid] = gb[1];
    }
    __syncthreads();

    const int    p  = chunk * PROPS_PER_CTA + tid;
    const size_t bp = (size_t)b * P + p;

    const float x = topk_index[bp * 3 + 0];
    const float y = topk_index[bp * 3 + 1];
    const float z = topk_index[bp * 3 + 2];

    // Hoist per-proposal gmem loads so their latency overlaps the loop.
    const float q0 = bbox_preds[bp * 2 + 0];
    const float q1 = bbox_preds[bp * 2 + 1];
    const float cf = topk_confs[bp];

    const uint64_t X2 = pack2(x, x);
    const uint64_t Y2 = pack2(y, y);
    const uint64_t Z2 = pack2(z, z);

    // Per-lane champions with strict < (first-index within each lane).
    // Lane a = even g (2i), lane b = odd g (2i+1).
    float besta = 3.402823466e38f, bestb = 3.402823466e38f;
    int   ia = 0, ib = 0;

    const int npairs = ((n + 7) & ~7) >> 1;    // multiple of 4 -> no remainder
    #pragma unroll 4
    for (int i = 0; i < npairs; ++i) {
        const ulonglong2 v   = spair[i][0];    // LDS.128: (-gx pair, -gy pair)
        const uint64_t   gnz = spair[i][1].x;  // LDS.64:  (-gz pair)

        const uint64_t dx = add2(X2, v.x);
        const uint64_t dy = add2(Y2, v.y);
        const uint64_t dz = add2(Z2, gnz);
        const uint64_t d2 = fma2(dx, dx, fma2(dy, dy, mul2(dz, dz)));

        float d2a, d2b;
        unpack2(d2, d2a, d2b);                 // free: reads the register pair
        if (d2a < besta) { besta = d2a; ia = i; }
        if (d2b < bestb) { bestb = d2b; ib = i; }
    }

    // Merge lanes. Exact JAX first-index argmin: on equal d2, the smaller
    // global index wins; 2*ib+1 < 2*ia  <=>  ib < ia.
    const int  idxa = 2 * ia;
    const int  idxb = 2 * ib + 1;
    const bool takeb = (bestb < besta) || ((bestb == besta) && (idxb < idxa));
    const float best = takeb ? bestb : besta;
    const int   bg   = takeb ? idxb  : idxa;

    // dist > 500  <=>  d2 > 500^2 (sqrt monotone; compare-exact)
    const float p2g = (best > DIST_T2) ? -1.0f : (float)bg;

    const float mb0 = sb0[bg];
    const float mb1 = sb1[bg];
    const bool cond = (p2g >= 0.0f) &&
                      ((q0 < mb0 - BBOX_THRESH) || (q1 < mb1 - BBOX_THRESH));

    // Stage outputs in shared (stride 7 coprime 32 -> conflict-free STS),
    // then copy the contiguous tile to GMEM as float4 (coalesced STG.128).
    float* so = sout + tid * 7;
    so[0] = x;  so[1] = y;  so[2] = z;
    so[3] = p2g; so[4] = cf;
    so[5] = cond ? mb0 : q0;
    so[6] = cond ? mb1 : q1;
    __syncthreads();

    const size_t tile_base = ((size_t)b * P + (size_t)chunk * PROPS_PER_CTA) * 7;
    float4*       dst = reinterpret_cast<float4*>(out + tile_base);
    const float4* src = reinterpret_cast<const float4*>(sout);
    constexpr int NVEC = PROPS_PER_CTA * 7 / 4;   // 224
    #pragma unroll
    for (int i = 0; i < 2; ++i) {
        const int idx = tid + i * THREADS;
        if (idx < NVEC) dst[idx] = src[idx];
    }
}

extern "C" void kernel_launch(void* const* d_in, const int* in_sizes, int n_in,
                              void* d_out, int out_size) {
    const float* topk_index  = (const float*)d_in[0];  // [B,P,3]
    const float* topk_confs  = (const float*)d_in[1];  // [B,P]
    const float* bbox_preds  = (const float*)d_in[2];  // [B,P,2]
    const float* gt_3d       = (const float*)d_in[3];  // [B,G,3]
    const float* gt_bbox     = (const float*)d_in[4];  // [B,G,2]
    const int*   num_person  = (const int*)  d_in[5];  // [B]
    float*       out         = (float*)d_out;          // [B,P,7]

    proposal_kernel<<<B * CHUNKS_PB, THREADS>>>(topk_index, topk_confs, bbox_preds,
                                                gt_3d, gt_bbox, num_person, out);
}